// round 6
// baseline (speedup 1.0000x reference)
#include <cuda_runtime.h>
#include <cstdint>
#include <cstddef>

#define T_STEPS 2048
#define N_ENV   256
#define HID     128
#define G3      384          // 3*HID
#define IDIM    128
#define M_TOTAL (T_STEPS*N_ENV)   // 524288
#define LDA     132          // padded smem row (floats)
#define RING    4            // gi ring depth (steps)

// Scratch for gi = x @ w_ih^T + b_ih : [M_TOTAL, G3] fp32 (805 MB)
__device__ float g_gi[(size_t)M_TOTAL * G3];

// ---------------------------------------------------------------------------
// helpers
// ---------------------------------------------------------------------------
__device__ __forceinline__ unsigned f2tf(float f){
  unsigned u; asm("cvt.rna.tf32.f32 %0, %1;" : "=r"(u) : "f"(f)); return u;
}
__device__ __forceinline__ void mma8(float* c, const unsigned* a, const unsigned* b){
  asm volatile("mma.sync.aligned.m16n8k8.row.col.f32.tf32.tf32.f32 "
      "{%0,%1,%2,%3}, {%4,%5,%6,%7}, {%8,%9}, {%0,%1,%2,%3};"
      : "+f"(c[0]), "+f"(c[1]), "+f"(c[2]), "+f"(c[3])
      : "r"(a[0]), "r"(a[1]), "r"(a[2]), "r"(a[3]), "r"(b[0]), "r"(b[1]));
}
__device__ __forceinline__ void cp16(float* dst, const float* src){
  unsigned s = (unsigned)__cvta_generic_to_shared(dst);
  asm volatile("cp.async.cg.shared.global [%0], [%1], 16;" :: "r"(s), "l"(src));
}
__device__ __forceinline__ void cp8(float* dst, const float* src){
  unsigned s = (unsigned)__cvta_generic_to_shared(dst);
  asm volatile("cp.async.ca.shared.global [%0], [%1], 8;" :: "r"(s), "l"(src));
}
__device__ __forceinline__ unsigned long long pk2(float lo, float hi){
  unsigned long long r; asm("mov.b64 %0, {%1,%2};" : "=l"(r) : "f"(lo), "f"(hi)); return r;
}
__device__ __forceinline__ void fma2(unsigned long long& d, unsigned long long a, unsigned long long b){
  asm("fma.rn.f32x2 %0, %1, %2, %0;" : "+l"(d) : "l"(a), "l"(b));
}
__device__ __forceinline__ unsigned long long add2(unsigned long long a, unsigned long long b){
  unsigned long long r; asm("add.rn.f32x2 %0, %1, %2;" : "=l"(r) : "l"(a), "l"(b)); return r;
}
__device__ __forceinline__ float2 upk(unsigned long long v){
  float lo, hi; asm("mov.b64 {%0,%1}, %2;" : "=f"(lo), "=f"(hi) : "l"(v));
  return make_float2(lo, hi);
}
__device__ __forceinline__ float sigf(float x){
  return __fdividef(1.0f, 1.0f + __expf(-x));
}
__device__ __forceinline__ float tanhf_(float x){
  return __fdividef(2.0f, 1.0f + __expf(-2.0f*x)) - 1.0f;
}

// ---------------------------------------------------------------------------
// K1: gi = x @ w_ih^T + b_ih   (tf32 mma.sync) — unchanged
// ---------------------------------------------------------------------------
__global__ void __launch_bounds__(256) k1_gi(const float* __restrict__ x,
                                             const float* __restrict__ w_ih,
                                             const float* __restrict__ b_ih){
  extern __shared__ float sm[];
  float* Bs   = sm;
  float* As   = sm + 128*LDA;
  float* bias = sm + 3*128*LDA;

  const int tid  = threadIdx.x;
  const int nb   = blockIdx.x;
  const int slab = blockIdx.y;
  const int gbase = nb * 128;

  for (int idx = tid; idx < 128*32; idx += 256){
    int r = idx >> 5, c4 = idx & 31;
    float4 v = reinterpret_cast<const float4*>(w_ih + (size_t)(gbase + r)*IDIM)[c4];
    float* d = Bs + r*LDA + c4*4;
    d[0] = __uint_as_float(f2tf(v.x));
    d[1] = __uint_as_float(f2tf(v.y));
    d[2] = __uint_as_float(f2tf(v.z));
    d[3] = __uint_as_float(f2tf(v.w));
  }
  if (tid < 128) bias[tid] = b_ih[gbase + tid];

  const int lane = tid & 31, wid = tid >> 5;
  const int wm = wid >> 1, wn = wid & 1;
  const int grp = lane >> 2, qid = lane & 3;

  {
    const float* srcb = x + (size_t)slab * 128 * IDIM;
    #pragma unroll
    for (int i = 0; i < 16; i++){
      int c = tid + 256*i;
      int r = c >> 5, c16 = c & 31;
      cp16(As + r*LDA + c16*4, srcb + (size_t)r*IDIM + c16*4);
    }
    asm volatile("cp.async.commit_group;");
  }

  for (int it = 0; it < 32; it++){
    const int buf = it & 1;
    if (it + 1 < 32){
      int mt = slab + (it+1)*128;
      const float* srcb = x + (size_t)mt * 128 * IDIM;
      float* dstb = As + ((it+1)&1)*128*LDA;
      #pragma unroll
      for (int i = 0; i < 16; i++){
        int c = tid + 256*i;
        int r = c >> 5, c16 = c & 31;
        cp16(dstb + r*LDA + c16*4, srcb + (size_t)r*IDIM + c16*4);
      }
      asm volatile("cp.async.commit_group;");
      asm volatile("cp.async.wait_group 1;");
    } else {
      asm volatile("cp.async.wait_group 0;");
    }
    __syncthreads();

    float c[2][8][4];
    #pragma unroll
    for (int am=0;am<2;am++)
      #pragma unroll
      for(int an=0;an<8;an++)
        #pragma unroll
        for(int k=0;k<4;k++) c[am][an][k]=0.f;

    const float* A = As + buf*128*LDA;
    for (int k0 = 0; k0 < 128; k0 += 8){
      unsigned af[2][4];
      #pragma unroll
      for (int am=0; am<2; am++){
        int r0 = wm*32 + am*16 + grp;
        af[am][0] = f2tf(A[r0*LDA + k0 + qid]);
        af[am][1] = f2tf(A[(r0+8)*LDA + k0 + qid]);
        af[am][2] = f2tf(A[r0*LDA + k0 + qid + 4]);
        af[am][3] = f2tf(A[(r0+8)*LDA + k0 + qid + 4]);
      }
      unsigned bf[8][2];
      #pragma unroll
      for (int an=0; an<8; an++){
        int nr = wn*64 + an*8 + grp;
        bf[an][0] = __float_as_uint(Bs[nr*LDA + k0 + qid]);
        bf[an][1] = __float_as_uint(Bs[nr*LDA + k0 + qid + 4]);
      }
      #pragma unroll
      for (int am=0; am<2; am++)
        #pragma unroll
        for (int an=0; an<8; an++)
          mma8(c[am][an], af[am], bf[an]);
    }
    __syncthreads();

    const int mrow = (slab + it*128) * 128;
    #pragma unroll
    for (int am=0; am<2; am++){
      int r0 = mrow + wm*32 + am*16 + grp;
      #pragma unroll
      for (int an=0; an<8; an++){
        int colL = wn*64 + an*8 + 2*qid;
        float b0 = bias[colL], b1 = bias[colL+1];
        float2 v0 = make_float2(c[am][an][0]+b0, c[am][an][1]+b1);
        float2 v1 = make_float2(c[am][an][2]+b0, c[am][an][3]+b1);
        *reinterpret_cast<float2*>(&g_gi[(size_t)r0*G3 + gbase + colL]) = v0;
        *reinterpret_cast<float2*>(&g_gi[(size_t)(r0+8)*G3 + gbase + colL]) = v1;
      }
    }
  }
}

// ---------------------------------------------------------------------------
// K2: persistent GRU scan. 128 CTAs x 768 threads (24 warps), 2 envs per CTA.
// Each w_hh row is split across TWO threads (k-halves); warp-uniform half so
// h LDS stays a single-address broadcast. Partial sums combined in smem by
// the gate threads. gi + masks staged via cp.async ring (2-step lookahead).
// Phase A(t): matvec env0 (all) -> psA || gates env1 step t-1 (warps 0-3, from psB)
// Phase B(t): matvec env1 (all) -> psB || gates env0 step t   (warps 0-3, from psA)
// ---------------------------------------------------------------------------
__global__ void __launch_bounds__(768, 1) k2_scan(
    const float* __restrict__ h0,
    const float* __restrict__ masks,
    const float* __restrict__ w_hh,
    const float* __restrict__ b_hh,
    float* __restrict__ outs,
    float* __restrict__ h_final)
{
  __shared__ __align__(16) float h_sm[2][HID];
  __shared__ float psA[2][G3];                           // [half][row], env0 matvec
  __shared__ float psB[2][G3];                           // [half][row], env1 matvec
  __shared__ __align__(16) float gi_ring[RING][2][G3];   // [slot][env][row]
  __shared__ __align__(8)  float m_ring[RING][2];        // [slot][env]

  const int g    = threadIdx.x;          // 0..767
  const int wrp  = g >> 5;               // 0..23
  const int lane = g & 31;
  const int half = wrp & 1;              // k-half: warp-uniform
  const int row  = (wrp >> 1) * 32 + lane;   // 0..383
  const int j    = g & 127;              // gate element (threads 0..127)
  const bool is_gate = (g < 128);
  const int e0 = blockIdx.x * 2;

  // half-row of w_hh: row `row`, k in [64*half, 64*half+64), packed f32x2 (64 regs)
  unsigned long long wq[32];
  {
    const float4* wr = reinterpret_cast<const float4*>(
        w_hh + (size_t)row * HID + 64*half);
    #pragma unroll
    for (int i = 0; i < 16; i++){
      float4 v = wr[i];
      wq[2*i]   = pk2(v.x, v.y);
      wq[2*i+1] = pk2(v.z, v.w);
    }
  }
  float bgr=0.f, bgz=0.f, bgn=0.f;
  if (is_gate){ bgr = b_hh[j]; bgz = b_hh[128+j]; bgn = b_hh[256+j]; }

  if (g < 256) h_sm[g>>7][j] = h0[(size_t)(e0 + (g>>7))*HID + j];

  const size_t STRIDE     = (size_t)N_ENV*G3;
  const size_t OUT_STRIDE = (size_t)N_ENV*HID;

  // cp.async staging: warps 12..17 (threads 384..575) move gi float4s,
  // thread 576 moves the two masks. Keeps gate warps 0-3 light.
  const int  cpk    = g - 384;
  const bool cp_gi  = (cpk >= 0) && (cpk < 192);
  const int  cp_env = (cpk >= 96);
  const int  cp_off = (cpk - cp_env*96) * 4;
  const float* gi_src_base = g_gi + (size_t)(e0 + cp_env)*G3 + cp_off;
  const float* mk_src_base = masks + e0;

  // Prologue: stage steps 0 and 1 (two committed groups)
  #pragma unroll
  for (int pt = 0; pt < 2; pt++){
    if (cp_gi)           cp16(&gi_ring[pt][cp_env][cp_off], gi_src_base + (size_t)pt*STRIDE);
    else if (cpk == 192) cp8(&m_ring[pt][0], mk_src_base + (size_t)pt*N_ENV);
    asm volatile("cp.async.commit_group;");
  }
  __syncthreads();

  #pragma unroll 1
  for (int t = 0; t < T_STEPS; t++){
    // Stage step t+2 (slot (t+2)&3); group t then guaranteed complete.
    if (t + 2 < T_STEPS){
      const int sl = (t+2) & (RING-1);
      if (cp_gi)           cp16(&gi_ring[sl][cp_env][cp_off], gi_src_base + (size_t)(t+2)*STRIDE);
      else if (cpk == 192) cp8(&m_ring[sl][0], mk_src_base + (size_t)(t+2)*N_ENV);
    }
    asm volatile("cp.async.commit_group;");
    asm volatile("cp.async.wait_group 2;");

    // ===== Phase A(t): gates env1 (step t-1, from psB) || matvec env0 ======
    if (is_gate && t > 0){
      const int sl = (t-1) & (RING-1);
      float cm = m_ring[sl][1];
      float cr = gi_ring[sl][1][j];
      float cz = gi_ring[sl][1][128+j];
      float cn = gi_ring[sl][1][256+j];
      float sr = psB[0][j]     + psB[1][j];
      float sz = psB[0][128+j] + psB[1][128+j];
      float sn = psB[0][256+j] + psB[1][256+j];
      float hold = h_sm[1][j];
      float r = sigf(cr + fmaf(cm, sr, bgr));
      float z = sigf(cz + fmaf(cm, sz, bgz));
      float n = tanhf_(cn + r * fmaf(cm, sn, bgn));
      float hn = fmaf(z, fmaf(cm, hold, -n), n);
      h_sm[1][j] = hn;
      outs[(size_t)(t-1)*OUT_STRIDE + (size_t)(e0+1)*HID + j] = hn;
    }
    {
      const ulonglong2* hp = reinterpret_cast<const ulonglong2*>(h_sm[0] + 64*half);
      unsigned long long A0=0, A1=0;
      #pragma unroll
      for (int i = 0; i < 16; i++){
        ulonglong2 v = hp[i];
        fma2(A0, wq[2*i],   v.x);
        fma2(A1, wq[2*i+1], v.y);
      }
      float2 f = upk(add2(A0, A1));
      psA[half][row] = f.x + f.y;
    }
    __syncthreads();

    // ===== Phase B(t): gates env0 (step t, from psA) || matvec env1 ========
    if (is_gate){
      const int sl = t & (RING-1);
      float cm = m_ring[sl][0];
      float cr = gi_ring[sl][0][j];
      float cz = gi_ring[sl][0][128+j];
      float cn = gi_ring[sl][0][256+j];
      float sr = psA[0][j]     + psA[1][j];
      float sz = psA[0][128+j] + psA[1][128+j];
      float sn = psA[0][256+j] + psA[1][256+j];
      float hold = h_sm[0][j];
      float r = sigf(cr + fmaf(cm, sr, bgr));
      float z = sigf(cz + fmaf(cm, sz, bgz));
      float n = tanhf_(cn + r * fmaf(cm, sn, bgn));
      float hn = fmaf(z, fmaf(cm, hold, -n), n);
      h_sm[0][j] = hn;
      outs[(size_t)t*OUT_STRIDE + (size_t)e0*HID + j] = hn;
      if (t == T_STEPS-1 && h_final != nullptr)
        h_final[(size_t)e0*HID + j] = hn;
    }
    {
      const ulonglong2* hp = reinterpret_cast<const ulonglong2*>(h_sm[1] + 64*half);
      unsigned long long A0=0, A1=0;
      #pragma unroll
      for (int i = 0; i < 16; i++){
        ulonglong2 v = hp[i];
        fma2(A0, wq[2*i],   v.x);
        fma2(A1, wq[2*i+1], v.y);
      }
      float2 f = upk(add2(A0, A1));
      psB[half][row] = f.x + f.y;
    }
    __syncthreads();
  }

  // ===== Epilogue: gates env1, step T-1 (psB + slot (T-1)&3) ===============
  if (is_gate){
    const int sl = (T_STEPS-1) & (RING-1);
    float cm = m_ring[sl][1];
    float cr = gi_ring[sl][1][j];
    float cz = gi_ring[sl][1][128+j];
    float cn = gi_ring[sl][1][256+j];
    float sr = psB[0][j]     + psB[1][j];
    float sz = psB[0][128+j] + psB[1][128+j];
    float sn = psB[0][256+j] + psB[1][256+j];
    float hold = h_sm[1][j];
    float r = sigf(cr + fmaf(cm, sr, bgr));
    float z = sigf(cz + fmaf(cm, sz, bgz));
    float n = tanhf_(cn + r * fmaf(cm, sn, bgn));
    float hn = fmaf(z, fmaf(cm, hold, -n), n);
    outs[(size_t)(T_STEPS-1)*OUT_STRIDE + (size_t)(e0+1)*HID + j] = hn;
    if (h_final != nullptr) h_final[(size_t)(e0+1)*HID + j] = hn;
  }
}

// ---------------------------------------------------------------------------
extern "C" void kernel_launch(void* const* d_in, const int* in_sizes, int n_in,
                              void* d_out, int out_size){
  (void)in_sizes; (void)n_in;
  const float* x     = (const float*)d_in[0];
  const float* h0    = (const float*)d_in[1];
  const float* masks = (const float*)d_in[2];
  const float* w_ih  = (const float*)d_in[3];
  const float* w_hh  = (const float*)d_in[4];
  const float* b_ih  = (const float*)d_in[5];
  const float* b_hh  = (const float*)d_in[6];

  float* outs = (float*)d_out;
  float* hf = nullptr;
  if ((long long)out_size >= (long long)M_TOTAL*HID + (long long)N_ENV*HID)
    hf = outs + (size_t)M_TOTAL*HID;

  const int k1_smem = (3*128*LDA + 128) * (int)sizeof(float);
  cudaFuncSetAttribute(k1_gi, cudaFuncAttributeMaxDynamicSharedMemorySize, k1_smem);
  k1_gi<<<dim3(3,128), 256, k1_smem>>>(x, w_ih, b_ih);
  k2_scan<<<128, 768>>>(h0, masks, w_hh, b_hh, outs, hf);
}